// round 2
// baseline (speedup 1.0000x reference)
#include <cuda_runtime.h>
#include <cuda_bf16.h>
#include <cstdint>

// Problem constants (SpaAggregator): B=16384, K=32, N=1e6, F=E=128
#define KNBR 32
#define FDIM 128
#define EDIM 128
#define MAXB 16384
#define NTBL 1000000

// Scratch for averaged features [B, F] (8 MB). __device__ global: no allocation.
__device__ float g_avg[(size_t)MAXB * FDIM];

// ---------------------------------------------------------------------------
// Kernel 1: gather + mean over K neighbors.
// One warp per output node b. Each lane owns one float4 (4 features).
// Row reads are fully coalesced 512B. 32 independent LDGs per lane => high MLP.
// Indices are int32 (JAX x64-disabled downcasts int64 -> int32).
// ---------------------------------------------------------------------------
__global__ __launch_bounds__(128) void gather_avg_kernel(
    const float* __restrict__ table,     // [N, 128]
    const int* __restrict__ idx,         // [B, 32] int32
    int B)
{
    const int warp = threadIdx.x >> 5;
    const int lane = threadIdx.x & 31;
    const int b = blockIdx.x * 4 + warp;
    if (b >= B) return;

    __shared__ int sidx[4][KNBR];
    int v0 = idx[(size_t)b * KNBR + lane];          // lane in [0,32) == KNBR
    v0 = min(max(v0, 0), NTBL - 1);                 // defensive clamp (free)
    sidx[warp][lane] = v0;
    __syncwarp();

    float4 acc = make_float4(0.f, 0.f, 0.f, 0.f);
    #pragma unroll
    for (int k = 0; k < KNBR; ++k) {
        const int r = sidx[warp][k];
        const float4 v = __ldg(reinterpret_cast<const float4*>(
                                   table + (size_t)r * FDIM) + lane);
        acc.x += v.x; acc.y += v.y; acc.z += v.z; acc.w += v.w;
    }
    const float s = 1.0f / (float)KNBR;
    acc.x *= s; acc.y *= s; acc.z *= s; acc.w *= s;
    reinterpret_cast<float4*>(g_avg + (size_t)b * FDIM)[lane] = acc;
}

// ---------------------------------------------------------------------------
// Kernel 2: out[B,128] = g_avg[B,128] @ W[128,128] + bias
// Tiled SGEMM: BM=64, BN=128 (full E), BK=16; 256 threads; 8x4 register tile.
// ---------------------------------------------------------------------------
#define BM 64
#define BN 128
#define BK 16
#define TM 8
#define TN 4
#define APAD 20   // padded row stride for As (multiple of 4 for float4 stores)

__global__ __launch_bounds__(256) void gemm_bias_kernel(
    const float* __restrict__ W,       // [128, 128]
    const float* __restrict__ bias,    // [128]
    float* __restrict__ out,           // [B, 128]
    int B)
{
    __shared__ float As[BM][APAD];     // A tile, row-major, padded
    __shared__ float Bs[BK][BN];       // W tile

    const int tid = threadIdx.x;
    const int tx = tid & 31;           // 0..31 -> column group (TN=4 -> 128 cols)
    const int ty = tid >> 5;           // 0..7  -> row group    (TM=8 -> 64 rows)
    const int block_m = blockIdx.x * BM;

    float acc[TM][TN] = {};

    for (int f0 = 0; f0 < FDIM; f0 += BK) {
        // --- load A tile: 64 rows x 16 cols. Thread: row = tid/4, quad = tid%4.
        {
            const int row = tid >> 2;        // 0..63
            const int q   = tid & 3;         // 0..3
            const float4 v = *reinterpret_cast<const float4*>(
                g_avg + (size_t)(block_m + row) * FDIM + f0 + q * 4);
            *reinterpret_cast<float4*>(&As[row][q * 4]) = v;
        }
        // --- load W tile: 16 rows x 128 cols = 2048 floats, 2 float4 per thread.
        #pragma unroll
        for (int i = 0; i < 2; ++i) {
            const int id  = tid + i * 256;   // 0..511
            const int row = id >> 5;         // 0..15
            const int c4  = id & 31;         // 0..31
            const float4 v = *reinterpret_cast<const float4*>(
                W + (size_t)(f0 + row) * EDIM + c4 * 4);
            *reinterpret_cast<float4*>(&Bs[row][c4 * 4]) = v;
        }
        __syncthreads();

        #pragma unroll
        for (int k = 0; k < BK; ++k) {
            float a[TM], bb[TN];
            #pragma unroll
            for (int i = 0; i < TM; ++i) a[i] = As[ty * TM + i][k];  // broadcast in warp
            #pragma unroll
            for (int j = 0; j < TN; ++j) bb[j] = Bs[k][tx * TN + j];
            #pragma unroll
            for (int i = 0; i < TM; ++i)
                #pragma unroll
                for (int j = 0; j < TN; ++j)
                    acc[i][j] += a[i] * bb[j];
        }
        __syncthreads();
    }

    #pragma unroll
    for (int i = 0; i < TM; ++i) {
        const int m = block_m + ty * TM + i;
        #pragma unroll
        for (int j = 0; j < TN; ++j) {
            const int e = tx * TN + j;
            out[(size_t)m * EDIM + e] = acc[i][j] + bias[e];
        }
    }
}

// ---------------------------------------------------------------------------
// Launch. Inputs per metadata order: id2feat f32 [N,128], weight f32 [128,128],
// bias f32 [128], neigh_idx int32 [B,32]. Output f32 [B,128].
// ---------------------------------------------------------------------------
extern "C" void kernel_launch(void* const* d_in, const int* in_sizes, int n_in,
                              void* d_out, int out_size)
{
    const float* id2feat = (const float*)d_in[0];
    const float* weight  = (const float*)d_in[1];
    const float* bias    = (const float*)d_in[2];
    const int*   nidx    = (const int*)d_in[3];
    float*       out     = (float*)d_out;

    int B = in_sizes[3] / KNBR;
    if (B > MAXB) B = MAXB;

    gather_avg_kernel<<<(B + 3) / 4, 128>>>(id2feat, nidx, B);
    gemm_bias_kernel<<<(B + BM - 1) / BM, 256>>>(weight, bias, out, B);
}

// round 3
// speedup vs baseline: 1.0190x; 1.0190x over previous
#include <cuda_runtime.h>
#include <cuda_bf16.h>
#include <cstdint>

// Problem constants (SpaAggregator): B=16384, K=32, N=1e6, F=E=128
#define KNBR 32
#define FDIM 128
#define EDIM 128
#define NTBL 1000000

#define BM   64          // nodes per CTA
#define NTHR 256         // 8 warps
#define ATP  66          // As_t row pad (even -> 8B-aligned LDS.64)

// Dynamic smem layout (bytes):
//   Ws   : 128*128*4 = 65536
//   As_t : 128*66*4  = 33792   (k-major averaged features)
//   sidx : 64*32*4   = 8192
#define SMEM_W    0
#define SMEM_AT   65536
#define SMEM_IDX  (65536 + 33792)
#define SMEM_TOT  (65536 + 33792 + 8192)

__device__ __forceinline__ unsigned long long ffma2(
    unsigned long long a, unsigned long long b, unsigned long long c)
{
    unsigned long long d;
    asm("fma.rn.f32x2 %0, %1, %2, %3;" : "=l"(d) : "l"(a), "l"(b), "l"(c));
    return d;
}
__device__ __forceinline__ unsigned long long pack2(float x, float y)
{
    unsigned long long r;
    asm("mov.b64 %0, {%1, %2};" : "=l"(r) : "f"(x), "f"(y));
    return r;
}
__device__ __forceinline__ void unpack2(unsigned long long v, float& x, float& y)
{
    asm("mov.b64 {%0, %1}, %2;" : "=f"(x), "=f"(y) : "l"(v));
}

// ---------------------------------------------------------------------------
// Fused: gather + mean(K=32) -> SMEM (k-major) -> GEMM vs W (SMEM) -> out
// ---------------------------------------------------------------------------
__global__ __launch_bounds__(NTHR, 2) void spa_fused_kernel(
    const float* __restrict__ table,   // [N, 128]
    const float* __restrict__ W,       // [128, 128]
    const float* __restrict__ bias,    // [128]
    const int*   __restrict__ idx,     // [B, 32] int32
    float*       __restrict__ out,     // [B, 128]
    int B)
{
    extern __shared__ char smem[];
    float* Ws   = reinterpret_cast<float*>(smem + SMEM_W);    // [128][128]
    float* As_t = reinterpret_cast<float*>(smem + SMEM_AT);   // [128][ATP]
    int*   sidx = reinterpret_cast<int*>  (smem + SMEM_IDX);  // [64][32]

    const int tid   = threadIdx.x;
    const int lane  = tid & 31;
    const int warp  = tid >> 5;
    const int blk_m = blockIdx.x * BM;

    // --- stage indices: 64 nodes * 32 = 2048 ints, 2 x int4 per thread -----
    {
        const int4* ip = reinterpret_cast<const int4*>(idx + (size_t)blk_m * KNBR);
        #pragma unroll
        for (int i = 0; i < 2; ++i) {
            int4 v = ip[tid + i * NTHR];
            v.x = min(max(v.x, 0), NTBL - 1);
            v.y = min(max(v.y, 0), NTBL - 1);
            v.z = min(max(v.z, 0), NTBL - 1);
            v.w = min(max(v.w, 0), NTBL - 1);
            reinterpret_cast<int4*>(sidx)[tid + i * NTHR] = v;
        }
    }

    // --- stage W: 16384 floats, 16 x float4 per thread (coalesced) ---------
    {
        const float4* wp = reinterpret_cast<const float4*>(W);
        float4*       ws = reinterpret_cast<float4*>(Ws);
        #pragma unroll
        for (int i = 0; i < 16; ++i)
            ws[tid + i * NTHR] = wp[tid + i * NTHR];
    }
    __syncthreads();   // sidx ready (Ws only needed after next sync)

    // --- gather + mean: warp per node, 8 nodes per warp ---------------------
    // lane owns features [4*lane, 4*lane+4); 32 independent 512B row reads.
    #pragma unroll 1
    for (int i = 0; i < BM / 8; ++i) {
        const int ln = warp * (BM / 8) + i;          // local node 0..63
        const int* nix = sidx + ln * KNBR;
        float4 acc = make_float4(0.f, 0.f, 0.f, 0.f);
        #pragma unroll
        for (int k = 0; k < KNBR; ++k) {
            const int r = nix[k];
            const float4 v = __ldg(reinterpret_cast<const float4*>(
                                       table + (size_t)r * FDIM) + lane);
            acc.x += v.x; acc.y += v.y; acc.z += v.z; acc.w += v.w;
        }
        const float s = 1.0f / (float)KNBR;
        float* base = As_t + (4 * lane) * ATP + ln;  // k-major store (transpose)
        base[0 * ATP] = acc.x * s;
        base[1 * ATP] = acc.y * s;
        base[2 * ATP] = acc.z * s;
        base[3 * ATP] = acc.w * s;
    }
    __syncthreads();   // As_t + Ws ready

    // --- GEMM: out[64][128] = As^T @ W + bias -------------------------------
    // Thread (ty=warp, tx=lane): rows ty*8..ty*8+7 (4 packed pairs), cols tx*4..+3.
    const int tx = lane, ty = warp;
    unsigned long long acc2[4][4];
    #pragma unroll
    for (int p = 0; p < 4; ++p)
        #pragma unroll
        for (int j = 0; j < 4; ++j) acc2[p][j] = 0ull;

    #pragma unroll 8
    for (int k = 0; k < FDIM; ++k) {
        // a row-pairs: broadcast LDS.64 (all lanes same address)
        const unsigned long long* ap = reinterpret_cast<const unsigned long long*>(
            As_t + k * ATP + ty * 8);
        unsigned long long a2[4];
        #pragma unroll
        for (int p = 0; p < 4; ++p) a2[p] = ap[p];

        // b: one LDS.128, duplicate each scalar into both f32x2 lanes
        const float4 bv = *reinterpret_cast<const float4*>(Ws + k * EDIM + tx * 4);
        unsigned long long b2[4];
        b2[0] = pack2(bv.x, bv.x);
        b2[1] = pack2(bv.y, bv.y);
        b2[2] = pack2(bv.z, bv.z);
        b2[3] = pack2(bv.w, bv.w);

        #pragma unroll
        for (int p = 0; p < 4; ++p)
            #pragma unroll
            for (int j = 0; j < 4; ++j)
                acc2[p][j] = ffma2(a2[p], b2[j], acc2[p][j]);
    }

    // --- epilogue: unpack pairs, add bias, store float4 per row ------------
    const float4 bb = *reinterpret_cast<const float4*>(bias + tx * 4);
    #pragma unroll
    for (int p = 0; p < 4; ++p) {
        const int m0 = blk_m + ty * 8 + 2 * p;
        float4 o0, o1;
        float lo, hi;
        unpack2(acc2[p][0], lo, hi); o0.x = lo + bb.x; o1.x = hi + bb.x;
        unpack2(acc2[p][1], lo, hi); o0.y = lo + bb.y; o1.y = hi + bb.y;
        unpack2(acc2[p][2], lo, hi); o0.z = lo + bb.z; o1.z = hi + bb.z;
        unpack2(acc2[p][3], lo, hi); o0.w = lo + bb.w; o1.w = hi + bb.w;
        *reinterpret_cast<float4*>(out + (size_t)m0 * EDIM + tx * 4)       = o0;
        *reinterpret_cast<float4*>(out + (size_t)(m0 + 1) * EDIM + tx * 4) = o1;
    }
}

// ---------------------------------------------------------------------------
// Launch. Inputs: id2feat f32 [N,128], weight f32 [128,128], bias f32 [128],
// neigh_idx int32 [B,32]. Output f32 [B,128].
// ---------------------------------------------------------------------------
extern "C" void kernel_launch(void* const* d_in, const int* in_sizes, int n_in,
                              void* d_out, int out_size)
{
    const float* id2feat = (const float*)d_in[0];
    const float* weight  = (const float*)d_in[1];
    const float* bias    = (const float*)d_in[2];
    const int*   nidx    = (const int*)d_in[3];
    float*       out     = (float*)d_out;

    const int B = in_sizes[3] / KNBR;

    cudaFuncSetAttribute(spa_fused_kernel,
                         cudaFuncAttributeMaxDynamicSharedMemorySize, SMEM_TOT);
    spa_fused_kernel<<<(B + BM - 1) / BM, NTHR, SMEM_TOT>>>(
        id2feat, weight, bias, nidx, out, B);
}

// round 4
// speedup vs baseline: 1.1800x; 1.1581x over previous
#include <cuda_runtime.h>
#include <cuda_bf16.h>
#include <cstdint>

// Problem constants (SpaAggregator): B=16384, K=32, N=1e6, F=E=128
#define KNBR 32
#define FDIM 128
#define EDIM 128
#define NTBL 1000000

#define BM   64          // nodes per CTA
#define NTHR 256         // 8 warps
#define ATP  66          // As_t row pad (even -> 8B-aligned LDS.64, conflict-skewed)

// Dynamic smem layout (bytes):  As_t 128*66*4 = 33792 ; sidx 64*32*4 = 8192
#define SMEM_AT   0
#define SMEM_IDX  33792
#define SMEM_TOT  (33792 + 8192)

__device__ __forceinline__ unsigned long long ffma2(
    unsigned long long a, unsigned long long b, unsigned long long c)
{
    unsigned long long d;
    asm("fma.rn.f32x2 %0, %1, %2, %3;" : "=l"(d) : "l"(a), "l"(b), "l"(c));
    return d;
}
__device__ __forceinline__ unsigned long long add2(
    unsigned long long a, unsigned long long b)
{
    unsigned long long d;
    asm("add.rn.f32x2 %0, %1, %2;" : "=l"(d) : "l"(a), "l"(b));
    return d;
}
__device__ __forceinline__ unsigned long long pack2(float x, float y)
{
    unsigned long long r;
    asm("mov.b64 %0, {%1, %2};" : "=l"(r) : "f"(x), "f"(y));
    return r;
}
__device__ __forceinline__ void unpack2(unsigned long long v, float& x, float& y)
{
    asm("mov.b64 {%0, %1}, %2;" : "=f"(x), "=f"(y) : "l"(v));
}

// ---------------------------------------------------------------------------
// Fused: gather + mean(K=32) -> SMEM (k-major) -> GEMM vs W (L1/L2) -> out
// 3 CTAs/SM resident: gather phases of some CTAs overlap GEMM of others.
// ---------------------------------------------------------------------------
__global__ __launch_bounds__(NTHR, 3) void spa_fused_kernel(
    const float* __restrict__ table,   // [N, 128]
    const float* __restrict__ W,       // [128, 128]
    const float* __restrict__ bias,    // [128]
    const int*   __restrict__ idx,     // [B, 32] int32
    float*       __restrict__ out,     // [B, 128]
    int B)
{
    extern __shared__ char smem[];
    float* As_t = reinterpret_cast<float*>(smem + SMEM_AT);   // [128][ATP]
    int*   sidx = reinterpret_cast<int*>  (smem + SMEM_IDX);  // [64][32]

    const int tid   = threadIdx.x;
    const int lane  = tid & 31;
    const int warp  = tid >> 5;
    const int blk_m = blockIdx.x * BM;

    // --- stage indices: 64 nodes * 32 = 2048 ints, 2 x int4 per thread -----
    {
        const int4* ip = reinterpret_cast<const int4*>(idx + (size_t)blk_m * KNBR);
        #pragma unroll
        for (int i = 0; i < 2; ++i) {
            int4 v = ip[tid + i * NTHR];
            v.x = min(max(v.x, 0), NTBL - 1);
            v.y = min(max(v.y, 0), NTBL - 1);
            v.z = min(max(v.z, 0), NTBL - 1);
            v.w = min(max(v.w, 0), NTBL - 1);
            reinterpret_cast<int4*>(sidx)[tid + i * NTHR] = v;
        }
    }
    __syncthreads();

    // --- gather + mean: warp per node, 8 nodes per warp ---------------------
    // lane owns features [4*lane, 4*lane+4); 32 coalesced 512B row reads/node.
    #pragma unroll 1
    for (int i = 0; i < BM / 8; ++i) {
        const int ln = warp * (BM / 8) + i;          // local node 0..63
        const int* nix = sidx + ln * KNBR;
        // two interleaved packed-f32x2 accumulator sets (break dep chain)
        unsigned long long aA0 = 0, aA1 = 0, aB0 = 0, aB1 = 0;
        #pragma unroll
        for (int k = 0; k < KNBR; k += 2) {
            const float4 v0 = __ldg(reinterpret_cast<const float4*>(
                                        table + (size_t)nix[k] * FDIM) + lane);
            const float4 v1 = __ldg(reinterpret_cast<const float4*>(
                                        table + (size_t)nix[k + 1] * FDIM) + lane);
            aA0 = add2(aA0, pack2(v0.x, v0.y));
            aA1 = add2(aA1, pack2(v0.z, v0.w));
            aB0 = add2(aB0, pack2(v1.x, v1.y));
            aB1 = add2(aB1, pack2(v1.z, v1.w));
        }
        float x0, x1, x2, x3, y0, y1, y2, y3;
        unpack2(aA0, x0, x1); unpack2(aA1, x2, x3);
        unpack2(aB0, y0, y1); unpack2(aB1, y2, y3);
        const float s = 1.0f / (float)KNBR;
        float* base = As_t + (4 * lane) * ATP + ln;  // k-major store (transpose)
        base[0 * ATP] = (x0 + y0) * s;
        base[1 * ATP] = (x1 + y1) * s;
        base[2 * ATP] = (x2 + y2) * s;
        base[3 * ATP] = (x3 + y3) * s;
    }
    __syncthreads();   // As_t ready

    // --- GEMM: out[64][128] = As^T @ W + bias -------------------------------
    // Thread (ty=warp, tx=lane): rows ty*8..+7 (4 packed pairs), cols tx*4..+3.
    // W read via __ldg: 8x reuse per CTA through L1, chip-wide through L2.
    const int tx = lane, ty = warp;
    unsigned long long acc2[4][4];
    #pragma unroll
    for (int p = 0; p < 4; ++p)
        #pragma unroll
        for (int j = 0; j < 4; ++j) acc2[p][j] = 0ull;

    const float4* wp = reinterpret_cast<const float4*>(W) + tx;  // row k: wp[k*32]

    #pragma unroll 8
    for (int k = 0; k < FDIM; ++k) {
        const float4 bv = __ldg(wp + k * 32);

        // a row-pairs: broadcast LDS.64 (all lanes in warp same address)
        const unsigned long long* ap = reinterpret_cast<const unsigned long long*>(
            As_t + k * ATP + ty * 8);
        unsigned long long a2[4];
        #pragma unroll
        for (int p = 0; p < 4; ++p) a2[p] = ap[p];

        unsigned long long b2[4];
        b2[0] = pack2(bv.x, bv.x);
        b2[1] = pack2(bv.y, bv.y);
        b2[2] = pack2(bv.z, bv.z);
        b2[3] = pack2(bv.w, bv.w);

        #pragma unroll
        for (int p = 0; p < 4; ++p)
            #pragma unroll
            for (int j = 0; j < 4; ++j)
                acc2[p][j] = ffma2(a2[p], b2[j], acc2[p][j]);
    }

    // --- epilogue: unpack pairs, add bias, store float4 per row ------------
    const float4 bb = *reinterpret_cast<const float4*>(bias + tx * 4);
    #pragma unroll
    for (int p = 0; p < 4; ++p) {
        const int m0 = blk_m + ty * 8 + 2 * p;
        float4 o0, o1;
        float lo, hi;
        unpack2(acc2[p][0], lo, hi); o0.x = lo + bb.x; o1.x = hi + bb.x;
        unpack2(acc2[p][1], lo, hi); o0.y = lo + bb.y; o1.y = hi + bb.y;
        unpack2(acc2[p][2], lo, hi); o0.z = lo + bb.z; o1.z = hi + bb.z;
        unpack2(acc2[p][3], lo, hi); o0.w = lo + bb.w; o1.w = hi + bb.w;
        *reinterpret_cast<float4*>(out + (size_t)m0 * EDIM + tx * 4)       = o0;
        *reinterpret_cast<float4*>(out + (size_t)(m0 + 1) * EDIM + tx * 4) = o1;
    }
}

// ---------------------------------------------------------------------------
// Launch. Inputs: id2feat f32 [N,128], weight f32 [128,128], bias f32 [128],
// neigh_idx int32 [B,32]. Output f32 [B,128].
// ---------------------------------------------------------------------------
extern "C" void kernel_launch(void* const* d_in, const int* in_sizes, int n_in,
                              void* d_out, int out_size)
{
    const float* id2feat = (const float*)d_in[0];
    const float* weight  = (const float*)d_in[1];
    const float* bias    = (const float*)d_in[2];
    const int*   nidx    = (const int*)d_in[3];
    float*       out     = (float*)d_out;

    const int B = in_sizes[3] / KNBR;

    cudaFuncSetAttribute(spa_fused_kernel,
                         cudaFuncAttributeMaxDynamicSharedMemorySize, SMEM_TOT);
    spa_fused_kernel<<<(B + BM - 1) / BM, NTHR, SMEM_TOT>>>(
        id2feat, weight, bias, nidx, out, B);
}

// round 5
// speedup vs baseline: 1.1821x; 1.0018x over previous
#include <cuda_runtime.h>
#include <cuda_bf16.h>
#include <cstdint>

// Problem constants (SpaAggregator): B=16384, K=32, N=1e6, F=E=128
#define KNBR 32
#define FDIM 128
#define EDIM 128
#define NTBL 1000000

#define BM   32          // nodes per CTA  -> grid = 512 for B=16384
#define NTHR 256         // 8 warps, 4 nodes per warp
#define ATP  34          // As_t row pad (even -> 8B-aligned LDS.64)

// Dynamic smem layout (bytes):  As_t 128*34*4 = 17408 ; sidx 32*32*4 = 4096
#define SMEM_AT   0
#define SMEM_IDX  17408
#define SMEM_TOT  (17408 + 4096)

__device__ __forceinline__ unsigned long long ffma2(
    unsigned long long a, unsigned long long b, unsigned long long c)
{
    unsigned long long d;
    asm("fma.rn.f32x2 %0, %1, %2, %3;" : "=l"(d) : "l"(a), "l"(b), "l"(c));
    return d;
}
__device__ __forceinline__ unsigned long long add2(
    unsigned long long a, unsigned long long b)
{
    unsigned long long d;
    asm("add.rn.f32x2 %0, %1, %2;" : "=l"(d) : "l"(a), "l"(b));
    return d;
}
__device__ __forceinline__ unsigned long long pack2(float x, float y)
{
    unsigned long long r;
    asm("mov.b64 %0, {%1, %2};" : "=l"(r) : "f"(x), "f"(y));
    return r;
}
__device__ __forceinline__ void unpack2(unsigned long long v, float& x, float& y)
{
    asm("mov.b64 {%0, %1}, %2;" : "=f"(x), "=f"(y) : "l"(v));
}

// ---------------------------------------------------------------------------
// Fused: gather + mean(K=32) -> SMEM (k-major) -> GEMM vs W (L1/L2) -> out
// Small CTA tile (BM=32) => 512 CTAs => ~3.5 CTAs/SM, single wave, high MLP.
// ---------------------------------------------------------------------------
__global__ __launch_bounds__(NTHR, 4) void spa_fused_kernel(
    const float* __restrict__ table,   // [N, 128]
    const float* __restrict__ W,       // [128, 128]
    const float* __restrict__ bias,    // [128]
    const int*   __restrict__ idx,     // [B, 32] int32
    float*       __restrict__ out,     // [B, 128]
    int B)
{
    extern __shared__ char smem[];
    float* As_t = reinterpret_cast<float*>(smem + SMEM_AT);   // [128][ATP]
    int*   sidx = reinterpret_cast<int*>  (smem + SMEM_IDX);  // [32][32]

    const int tid   = threadIdx.x;
    const int lane  = tid & 31;
    const int warp  = tid >> 5;
    const int blk_m = blockIdx.x * BM;

    // --- stage indices: 32 nodes * 32 = 1024 ints, 1 x int4 per thread -----
    {
        const int4* ip = reinterpret_cast<const int4*>(idx + (size_t)blk_m * KNBR);
        int4 v = ip[tid];
        v.x = min(max(v.x, 0), NTBL - 1);
        v.y = min(max(v.y, 0), NTBL - 1);
        v.z = min(max(v.z, 0), NTBL - 1);
        v.w = min(max(v.w, 0), NTBL - 1);
        reinterpret_cast<int4*>(sidx)[tid] = v;
    }
    __syncthreads();

    // --- gather + mean: warp per node, 4 nodes per warp ---------------------
    // lane owns features [4*lane, 4*lane+4); 32 coalesced 512B row reads/node.
    #pragma unroll 1
    for (int i = 0; i < BM / 8; ++i) {
        const int ln = warp * (BM / 8) + i;          // local node 0..31
        const int* nix = sidx + ln * KNBR;
        // two interleaved packed-f32x2 accumulator sets (break dep chain)
        unsigned long long aA0 = 0, aA1 = 0, aB0 = 0, aB1 = 0;
        #pragma unroll
        for (int k = 0; k < KNBR; k += 2) {
            const float4 v0 = __ldg(reinterpret_cast<const float4*>(
                                        table + (size_t)nix[k] * FDIM) + lane);
            const float4 v1 = __ldg(reinterpret_cast<const float4*>(
                                        table + (size_t)nix[k + 1] * FDIM) + lane);
            aA0 = add2(aA0, pack2(v0.x, v0.y));
            aA1 = add2(aA1, pack2(v0.z, v0.w));
            aB0 = add2(aB0, pack2(v1.x, v1.y));
            aB1 = add2(aB1, pack2(v1.z, v1.w));
        }
        float x0, x1, x2, x3, y0, y1, y2, y3;
        unpack2(aA0, x0, x1); unpack2(aA1, x2, x3);
        unpack2(aB0, y0, y1); unpack2(aB1, y2, y3);
        const float s = 1.0f / (float)KNBR;
        float* base = As_t + (4 * lane) * ATP + ln;  // k-major store (transpose)
        base[0 * ATP] = (x0 + y0) * s;
        base[1 * ATP] = (x1 + y1) * s;
        base[2 * ATP] = (x2 + y2) * s;
        base[3 * ATP] = (x3 + y3) * s;
    }
    __syncthreads();   // As_t ready

    // --- GEMM: out[32][128] = As^T @ W + bias -------------------------------
    // Thread (ty=warp, tx=lane): rows ty*4..+3 (2 packed pairs), cols tx*4..+3.
    // W read via __ldg: 8x reuse per CTA through L1, chip-wide through L2.
    const int tx = lane, ty = warp;
    unsigned long long acc2[2][4];
    #pragma unroll
    for (int p = 0; p < 2; ++p)
        #pragma unroll
        for (int j = 0; j < 4; ++j) acc2[p][j] = 0ull;

    const float4* wp = reinterpret_cast<const float4*>(W) + tx;  // row k: wp[k*32]

    #pragma unroll 8
    for (int k = 0; k < FDIM; ++k) {
        const float4 bv = __ldg(wp + k * 32);

        // a row-pairs: broadcast LDS.64 (all lanes in warp same address)
        const unsigned long long* ap = reinterpret_cast<const unsigned long long*>(
            As_t + k * ATP + ty * 4);
        unsigned long long a2[2];
        a2[0] = ap[0];
        a2[1] = ap[1];

        unsigned long long b2[4];
        b2[0] = pack2(bv.x, bv.x);
        b2[1] = pack2(bv.y, bv.y);
        b2[2] = pack2(bv.z, bv.z);
        b2[3] = pack2(bv.w, bv.w);

        #pragma unroll
        for (int p = 0; p < 2; ++p)
            #pragma unroll
            for (int j = 0; j < 4; ++j)
                acc2[p][j] = ffma2(a2[p], b2[j], acc2[p][j]);
    }

    // --- epilogue: unpack pairs, add bias, store float4 per row ------------
    const float4 bb = *reinterpret_cast<const float4*>(bias + tx * 4);
    #pragma unroll
    for (int p = 0; p < 2; ++p) {
        const int m0 = blk_m + ty * 4 + 2 * p;
        float4 o0, o1;
        float lo, hi;
        unpack2(acc2[p][0], lo, hi); o0.x = lo + bb.x; o1.x = hi + bb.x;
        unpack2(acc2[p][1], lo, hi); o0.y = lo + bb.y; o1.y = hi + bb.y;
        unpack2(acc2[p][2], lo, hi); o0.z = lo + bb.z; o1.z = hi + bb.z;
        unpack2(acc2[p][3], lo, hi); o0.w = lo + bb.w; o1.w = hi + bb.w;
        *reinterpret_cast<float4*>(out + (size_t)m0 * EDIM + tx * 4)       = o0;
        *reinterpret_cast<float4*>(out + (size_t)(m0 + 1) * EDIM + tx * 4) = o1;
    }
}

// ---------------------------------------------------------------------------
// Launch. Inputs: id2feat f32 [N,128], weight f32 [128,128], bias f32 [128],
// neigh_idx int32 [B,32]. Output f32 [B,128].
// ---------------------------------------------------------------------------
extern "C" void kernel_launch(void* const* d_in, const int* in_sizes, int n_in,
                              void* d_out, int out_size)
{
    const float* id2feat = (const float*)d_in[0];
    const float* weight  = (const float*)d_in[1];
    const float* bias    = (const float*)d_in[2];
    const int*   nidx    = (const int*)d_in[3];
    float*       out     = (float*)d_out;

    const int B = in_sizes[3] / KNBR;

    cudaFuncSetAttribute(spa_fused_kernel,
                         cudaFuncAttributeMaxDynamicSharedMemorySize, SMEM_TOT);
    spa_fused_kernel<<<(B + BM - 1) / BM, NTHR, SMEM_TOT>>>(
        id2feat, weight, bias, nidx, out, B);
}

// round 6
// speedup vs baseline: 1.2229x; 1.0345x over previous
#include <cuda_runtime.h>
#include <cuda_bf16.h>
#include <cstdint>

// Problem constants (SpaAggregator): B=16384, K=32, N=1e6, F=E=128
#define KNBR 32
#define FDIM 128
#define EDIM 128
#define NTBL 1000000

#define BM    32         // nodes per CTA -> grid = 512 for B=16384
#define NTHR  256        // 8 warps: 4 producer + 4 consumer
#define TILE  16         // nodes per pipeline tile (2 tiles per CTA)
#define ATP   20         // As_t row stride in floats (16 + pad; 80B, 16B-aligned)

// Dynamic smem (bytes): As_t[2] tiles 2*128*20*4 = 20480 ; sidx 32*32*4 = 4096
#define SMEM_AT   0
#define SMEM_IDX  20480
#define SMEM_TOT  (20480 + 4096)

__device__ __forceinline__ unsigned long long ffma2(
    unsigned long long a, unsigned long long b, unsigned long long c)
{
    unsigned long long d;
    asm("fma.rn.f32x2 %0, %1, %2, %3;" : "=l"(d) : "l"(a), "l"(b), "l"(c));
    return d;
}
__device__ __forceinline__ unsigned long long add2(
    unsigned long long a, unsigned long long b)
{
    unsigned long long d;
    asm("add.rn.f32x2 %0, %1, %2;" : "=l"(d) : "l"(a), "l"(b));
    return d;
}
__device__ __forceinline__ unsigned long long pack2(float x, float y)
{
    unsigned long long r;
    asm("mov.b64 %0, {%1, %2};" : "=l"(r) : "f"(x), "f"(y));
    return r;
}
__device__ __forceinline__ void unpack2(unsigned long long v, float& x, float& y)
{
    asm("mov.b64 {%0, %1}, %2;" : "=f"(x), "=f"(y) : "l"(v));
}

// ---------------------------------------------------------------------------
// Warp-specialized fused kernel:
//   warps 0-3: gather + mean -> As_t tile ring (k-major), bar.arrive
//   warps 4-7: bar.sync, GEMM tile vs W (L1/L2), +bias, store out
// Producers' issue stream is pure LDG/ADD2 (deep MLP); consumers' FFMA work
// overlaps the next tile's DRAM stream instead of serializing after it.
// ---------------------------------------------------------------------------
__global__ __launch_bounds__(NTHR, 4) void spa_fused_ws_kernel(
    const float* __restrict__ table,   // [N, 128]
    const float* __restrict__ W,       // [128, 128]
    const float* __restrict__ bias,    // [128]
    const int*   __restrict__ idx,     // [B, 32] int32
    float*       __restrict__ out,     // [B, 128]
    int B)
{
    extern __shared__ char smem[];
    float* As_t = reinterpret_cast<float*>(smem + SMEM_AT);   // [2][128][ATP]
    int*   sidx = reinterpret_cast<int*>  (smem + SMEM_IDX);  // [32][32]

    const int tid   = threadIdx.x;
    const int lane  = tid & 31;
    const int warp  = tid >> 5;
    const int blk_m = blockIdx.x * BM;

    // --- stage indices: 1024 ints, int4 per thread (all warps) -------------
    {
        const int4* ip = reinterpret_cast<const int4*>(idx + (size_t)blk_m * KNBR);
        int4 v = ip[tid];
        v.x = min(max(v.x, 0), NTBL - 1);
        v.y = min(max(v.y, 0), NTBL - 1);
        v.z = min(max(v.z, 0), NTBL - 1);
        v.w = min(max(v.w, 0), NTBL - 1);
        reinterpret_cast<int4*>(sidx)[tid] = v;
    }
    __syncthreads();

    if (warp < 4) {
        // =============== PRODUCER: gather + mean ===========================
        // tile t: nodes [t*16, t*16+16); this warp: 4 nodes per tile.
        #pragma unroll 1
        for (int t = 0; t < 2; ++t) {
            float* At = As_t + t * (128 * ATP);
            #pragma unroll 1
            for (int i = 0; i < TILE / 4; ++i) {
                const int c  = warp * 4 + i;          // column within tile
                const int ln = t * TILE + c;          // local node 0..31
                const int* nix = sidx + ln * KNBR;
                unsigned long long aA0 = 0, aA1 = 0, aB0 = 0, aB1 = 0;
                #pragma unroll
                for (int k = 0; k < KNBR; k += 2) {
                    const float4 v0 = __ldg(reinterpret_cast<const float4*>(
                                                table + (size_t)nix[k] * FDIM) + lane);
                    const float4 v1 = __ldg(reinterpret_cast<const float4*>(
                                                table + (size_t)nix[k + 1] * FDIM) + lane);
                    aA0 = add2(aA0, pack2(v0.x, v0.y));
                    aA1 = add2(aA1, pack2(v0.z, v0.w));
                    aB0 = add2(aB0, pack2(v1.x, v1.y));
                    aB1 = add2(aB1, pack2(v1.z, v1.w));
                }
                float x0, x1, x2, x3, y0, y1, y2, y3;
                unpack2(aA0, x0, x1); unpack2(aA1, x2, x3);
                unpack2(aB0, y0, y1); unpack2(aB1, y2, y3);
                const float s = 1.0f / (float)KNBR;
                float* base = At + (4 * lane) * ATP + c;   // k-major store
                base[0 * ATP] = (x0 + y0) * s;
                base[1 * ATP] = (x1 + y1) * s;
                base[2 * ATP] = (x2 + y2) * s;
                base[3 * ATP] = (x3 + y3) * s;
            }
            // signal tile t ready (barrier id t+1, total count = 256)
            if (t == 0) asm volatile("bar.arrive 1, 256;" ::: "memory");
            else        asm volatile("bar.arrive 2, 256;" ::: "memory");
        }
    } else {
        // =============== CONSUMER: GEMM + bias + store ======================
        const int w4 = warp - 4;                 // 0..3: rows w4*4..+3 of tile
        const int tx = lane;
        const float4* wp = reinterpret_cast<const float4*>(W) + tx;  // W[k][4tx..]
        const float4 bb = *reinterpret_cast<const float4*>(bias + tx * 4);

        #pragma unroll 1
        for (int t = 0; t < 2; ++t) {
            if (t == 0) asm volatile("bar.sync 1, 256;" ::: "memory");
            else        asm volatile("bar.sync 2, 256;" ::: "memory");

            const float* At = As_t + t * (128 * ATP);
            unsigned long long acc2[2][4];
            #pragma unroll
            for (int p = 0; p < 2; ++p)
                #pragma unroll
                for (int j = 0; j < 4; ++j) acc2[p][j] = 0ull;

            #pragma unroll 8
            for (int k = 0; k < FDIM; ++k) {
                const float4 bv = __ldg(wp + k * 32);
                // a: 4 consecutive nodes = 2 packed pairs, one LDS.128 (broadcast)
                const ulonglong2 av = *reinterpret_cast<const ulonglong2*>(
                    At + k * ATP + w4 * 4);
                unsigned long long b2[4];
                b2[0] = pack2(bv.x, bv.x);
                b2[1] = pack2(bv.y, bv.y);
                b2[2] = pack2(bv.z, bv.z);
                b2[3] = pack2(bv.w, bv.w);
                #pragma unroll
                for (int j = 0; j < 4; ++j) {
                    acc2[0][j] = ffma2(av.x, b2[j], acc2[0][j]);
                    acc2[1][j] = ffma2(av.y, b2[j], acc2[1][j]);
                }
            }

            #pragma unroll
            for (int p = 0; p < 2; ++p) {
                const int m0 = blk_m + t * TILE + w4 * 4 + 2 * p;
                float4 o0, o1;
                float lo, hi;
                unpack2(acc2[p][0], lo, hi); o0.x = lo + bb.x; o1.x = hi + bb.x;
                unpack2(acc2[p][1], lo, hi); o0.y = lo + bb.y; o1.y = hi + bb.y;
                unpack2(acc2[p][2], lo, hi); o0.z = lo + bb.z; o1.z = hi + bb.z;
                unpack2(acc2[p][3], lo, hi); o0.w = lo + bb.w; o1.w = hi + bb.w;
                *reinterpret_cast<float4*>(out + (size_t)m0 * EDIM + tx * 4)       = o0;
                *reinterpret_cast<float4*>(out + (size_t)(m0 + 1) * EDIM + tx * 4) = o1;
            }
        }
    }
}

// ---------------------------------------------------------------------------
// Launch. Inputs: id2feat f32 [N,128], weight f32 [128,128], bias f32 [128],
// neigh_idx int32 [B,32]. Output f32 [B,128].
// ---------------------------------------------------------------------------
extern "C" void kernel_launch(void* const* d_in, const int* in_sizes, int n_in,
                              void* d_out, int out_size)
{
    const float* id2feat = (const float*)d_in[0];
    const float* weight  = (const float*)d_in[1];
    const float* bias    = (const float*)d_in[2];
    const int*   nidx    = (const int*)d_in[3];
    float*       out     = (float*)d_out;

    const int B = in_sizes[3] / KNBR;

    cudaFuncSetAttribute(spa_fused_ws_kernel,
                         cudaFuncAttributeMaxDynamicSharedMemorySize, SMEM_TOT);
    spa_fused_ws_kernel<<<(B + BM - 1) / BM, NTHR, SMEM_TOT>>>(
        id2feat, weight, bias, nidx, out, B);
}